// round 3
// baseline (speedup 1.0000x reference)
#include <cuda_runtime.h>
#include <math.h>

#define NTOK 16384            // B*S = 4*4096
#define DMODEL 1024

// Scratch (allocation-free rule: __device__ globals).
// g_big: holds qkv (48M floats) in stages 1-2, then h (64M floats) in 3-4.
__device__ float g_big[(size_t)NTOK * 4096];   // 256 MB
__device__ float g_x1 [(size_t)NTOK * 1024];   // 64 MB: post-attention LN out
__device__ float g_ffn[(size_t)NTOK * 1024];   // 64 MB: ffn_out

// ---------------------------------------------------------------------------
// Tiled fp32 GEMM: C[M,N] = A[M,K] @ B[K,N] + bias[N], optional exact GELU.
// BM=BN=128, BK=16, 256 threads, 8x8 per-thread microtile.
// Double-buffered shared memory: global loads for tile t+1 issue before the
// FFMA loop over tile t, one __syncthreads per K-step.
// ---------------------------------------------------------------------------
template<int EPI>   // 0 = bias, 1 = bias + gelu(exact)
__global__ __launch_bounds__(256) void gemm_kernel(
    const float* __restrict__ A, const float* __restrict__ B,
    const float* __restrict__ bias, float* __restrict__ C,
    int M, int N, int K)
{
    constexpr int BM = 128, BN = 128, BK = 16;
    __shared__ float As[2][BK][BM];   // transposed A tile
    __shared__ float Bs[2][BK][BN];

    const int tid = threadIdx.x;
    const int bm = blockIdx.y * BM;
    const int bn = blockIdx.x * BN;
    const int tx = tid & 15;
    const int ty = tid >> 4;

    float acc[8][8] = {};

    // A tile: 128 rows x 16 cols = 512 float4 (along K). Each thread: 2 float4.
    const int aRow  = tid >> 1;
    const int aCol4 = (tid * 2) & 3;     // even tid: {0,1}, odd tid: {2,3}

    const int NT = K / BK;

    float4 fa[2], fb[2];

    // ---- prologue: fetch tile 0 ----
    #pragma unroll
    for (int i = 0; i < 2; i++) {
        fa[i] = *(const float4*)(A + (size_t)(bm + aRow) * K + (aCol4 + i) * 4);
        int v = tid * 2 + i;
        fb[i] = *(const float4*)(B + (size_t)(v >> 5) * N + bn + (v & 31) * 4);
    }
    #pragma unroll
    for (int i = 0; i < 2; i++) {
        int col4 = aCol4 + i;
        As[0][col4 * 4 + 0][aRow] = fa[i].x;
        As[0][col4 * 4 + 1][aRow] = fa[i].y;
        As[0][col4 * 4 + 2][aRow] = fa[i].z;
        As[0][col4 * 4 + 3][aRow] = fa[i].w;
        int v = tid * 2 + i;
        *(float4*)&Bs[0][v >> 5][(v & 31) * 4] = fb[i];
    }
    __syncthreads();

    for (int kt = 0; kt < NT; kt++) {
        const int cur = kt & 1;

        // ---- prefetch tile kt+1 into registers (overlaps with compute) ----
        if (kt + 1 < NT) {
            int k0 = (kt + 1) * BK;
            #pragma unroll
            for (int i = 0; i < 2; i++) {
                fa[i] = *(const float4*)(A + (size_t)(bm + aRow) * K + k0 + (aCol4 + i) * 4);
                int v = tid * 2 + i;
                fb[i] = *(const float4*)(B + (size_t)(k0 + (v >> 5)) * N + bn + (v & 31) * 4);
            }
        }

        // ---- compute on current buffer ----
        #pragma unroll
        for (int k = 0; k < BK; k++) {
            float ra[8], rb[8];
            #pragma unroll
            for (int i = 0; i < 8; i++) ra[i] = As[cur][k][ty * 8 + i];
            #pragma unroll
            for (int j = 0; j < 8; j++) rb[j] = Bs[cur][k][tx * 8 + j];
            #pragma unroll
            for (int i = 0; i < 8; i++)
                #pragma unroll
                for (int j = 0; j < 8; j++)
                    acc[i][j] += ra[i] * rb[j];
        }

        // ---- store prefetched tile into the other buffer ----
        if (kt + 1 < NT) {
            const int nxt = cur ^ 1;
            #pragma unroll
            for (int i = 0; i < 2; i++) {
                int col4 = aCol4 + i;
                As[nxt][col4 * 4 + 0][aRow] = fa[i].x;
                As[nxt][col4 * 4 + 1][aRow] = fa[i].y;
                As[nxt][col4 * 4 + 2][aRow] = fa[i].z;
                As[nxt][col4 * 4 + 3][aRow] = fa[i].w;
                int v = tid * 2 + i;
                *(float4*)&Bs[nxt][v >> 5][(v & 31) * 4] = fb[i];
            }
            __syncthreads();
        }
    }

    #pragma unroll
    for (int i = 0; i < 8; i++) {
        int m = bm + ty * 8 + i;
        #pragma unroll
        for (int j = 0; j < 8; j++) {
            int n = bn + tx * 8 + j;
            float v = acc[i][j] + bias[n];
            if (EPI == 1) v = 0.5f * v * (1.0f + erff(v * 0.7071067811865476f));
            C[(size_t)m * N + n] = v;
        }
    }
}

// ---------------------------------------------------------------------------
// Fused per-token head-mix "attention" + residual + LayerNorm.
// One block (256 threads) per token. q,k,v are the 3x16x64 slices of the qkv
// row. Padded smem stride 65 -> conflict-free k[g*stride+d] access.
// ---------------------------------------------------------------------------
__global__ __launch_bounds__(256) void attn_ln_kernel(
    const float* __restrict__ qkv, const float* __restrict__ x,
    const float* __restrict__ g1, const float* __restrict__ beta1,
    float* __restrict__ x1)
{
    __shared__ float sPad[3 * 16 * 65];   // q,k,v padded [16][65]
    __shared__ float sP[256];             // scores / attn
    __shared__ float wred[16];

    const int token = blockIdx.x;
    const int tid = threadIdx.x;
    const float* row = qkv + (size_t)token * 3072;

    for (int i = tid; i < 3072; i += 256) {
        int sec = i >> 10, r = (i & 1023) >> 6, d = i & 63;
        sPad[sec * 1040 + r * 65 + d] = row[i];
    }
    __syncthreads();

    const float* sQ = sPad;
    const float* sK = sPad + 1040;
    const float* sV = sPad + 2080;

    const int h = tid >> 4, g = tid & 15;
    float s = 0.f;
    #pragma unroll
    for (int d = 0; d < 64; d++) s += sQ[h * 65 + d] * sK[g * 65 + d];
    sP[tid] = s * 0.125f;   // 1/sqrt(64)
    __syncthreads();

    float rv[16];
    #pragma unroll
    for (int j = 0; j < 16; j++) rv[j] = sP[h * 16 + j];
    float mx = rv[0];
    #pragma unroll
    for (int j = 1; j < 16; j++) mx = fmaxf(mx, rv[j]);
    float sum = 0.f;
    #pragma unroll
    for (int j = 0; j < 16; j++) sum += __expf(rv[j] - mx);
    float attn = __expf(rv[g] - mx) / sum;
    __syncthreads();
    sP[tid] = attn;
    __syncthreads();

    const float* xr = x + (size_t)token * 1024;
    float y[4];
    #pragma unroll
    for (int i = 0; i < 4; i++) {
        int idx = tid + i * 256;
        int hh = idx >> 6, d = idx & 63;
        float a = 0.f;
        #pragma unroll
        for (int gg = 0; gg < 16; gg++) a += sP[hh * 16 + gg] * sV[gg * 65 + d];
        y[i] = a + xr[idx];
    }

    // block reduce mean / var
    float lsum = y[0] + y[1] + y[2] + y[3];
    float lsq  = y[0]*y[0] + y[1]*y[1] + y[2]*y[2] + y[3]*y[3];
    #pragma unroll
    for (int o = 16; o > 0; o >>= 1) {
        lsum += __shfl_down_sync(0xffffffffu, lsum, o);
        lsq  += __shfl_down_sync(0xffffffffu, lsq,  o);
    }
    const int wid = tid >> 5, lane = tid & 31;
    if (lane == 0) { wred[wid] = lsum; wred[8 + wid] = lsq; }
    __syncthreads();
    float tot = 0.f, totsq = 0.f;
    #pragma unroll
    for (int i = 0; i < 8; i++) { tot += wred[i]; totsq += wred[8 + i]; }
    float mu  = tot * (1.0f / 1024.0f);
    float var = totsq * (1.0f / 1024.0f) - mu * mu;
    float inv = rsqrtf(var + 1e-5f);

    float* o = x1 + (size_t)token * 1024;
    #pragma unroll
    for (int i = 0; i < 4; i++) {
        int idx = tid + i * 256;
        o[idx] = (y[i] - mu) * inv * g1[idx] + beta1[idx];
    }
}

// ---------------------------------------------------------------------------
// Final residual + LayerNorm: out = LN(a + b) * g + beta. One block per token.
// ---------------------------------------------------------------------------
__global__ __launch_bounds__(256) void resid_ln_kernel(
    const float* __restrict__ a, const float* __restrict__ b,
    const float* __restrict__ g, const float* __restrict__ beta,
    float* __restrict__ out)
{
    __shared__ float wred[16];
    const int token = blockIdx.x;
    const int tid = threadIdx.x;
    const float* ar = a + (size_t)token * 1024;
    const float* br = b + (size_t)token * 1024;

    float y[4];
    #pragma unroll
    for (int i = 0; i < 4; i++) {
        int idx = tid + i * 256;
        y[i] = ar[idx] + br[idx];
    }
    float lsum = y[0] + y[1] + y[2] + y[3];
    float lsq  = y[0]*y[0] + y[1]*y[1] + y[2]*y[2] + y[3]*y[3];
    #pragma unroll
    for (int o = 16; o > 0; o >>= 1) {
        lsum += __shfl_down_sync(0xffffffffu, lsum, o);
        lsq  += __shfl_down_sync(0xffffffffu, lsq,  o);
    }
    const int wid = tid >> 5, lane = tid & 31;
    if (lane == 0) { wred[wid] = lsum; wred[8 + wid] = lsq; }
    __syncthreads();
    float tot = 0.f, totsq = 0.f;
    #pragma unroll
    for (int i = 0; i < 8; i++) { tot += wred[i]; totsq += wred[8 + i]; }
    float mu  = tot * (1.0f / 1024.0f);
    float var = totsq * (1.0f / 1024.0f) - mu * mu;
    float inv = rsqrtf(var + 1e-5f);

    float* o = out + (size_t)token * 1024;
    #pragma unroll
    for (int i = 0; i < 4; i++) {
        int idx = tid + i * 256;
        o[idx] = (y[i] - mu) * inv * g[idx] + beta[idx];
    }
}

// ---------------------------------------------------------------------------
extern "C" void kernel_launch(void* const* d_in, const int* in_sizes, int n_in,
                              void* d_out, int out_size)
{
    const float* x    = (const float*)d_in[0];
    const float* Wqkv = (const float*)d_in[1];
    const float* bqkv = (const float*)d_in[2];
    const float* W1   = (const float*)d_in[3];
    const float* b1   = (const float*)d_in[4];
    const float* W2   = (const float*)d_in[5];
    const float* b2   = (const float*)d_in[6];
    const float* g1   = (const float*)d_in[7];
    const float* be1  = (const float*)d_in[8];
    const float* g2   = (const float*)d_in[9];
    const float* be2  = (const float*)d_in[10];
    float* out = (float*)d_out;

    float *big, *x1, *ffn;
    cudaGetSymbolAddress((void**)&big, g_big);
    cudaGetSymbolAddress((void**)&x1,  g_x1);
    cudaGetSymbolAddress((void**)&ffn, g_ffn);
    float* qkv = big;   // stages 1-2 (48M floats)
    float* h   = big;   // stages 3-4 (64M floats) — qkv dead after stage 2

    // 1) qkv = x @ Wqkv + bqkv          (16384x1024 @ 1024x3072)
    gemm_kernel<0><<<dim3(3072 / 128, NTOK / 128), 256>>>(x, Wqkv, bqkv, qkv,
                                                          NTOK, 3072, 1024);
    // 2) x1 = LN(x + headmix(qkv))
    attn_ln_kernel<<<NTOK, 256>>>(qkv, x, g1, be1, x1);
    // 3) h = gelu(x1 @ W1 + b1)         (16384x1024 @ 1024x4096)
    gemm_kernel<1><<<dim3(4096 / 128, NTOK / 128), 256>>>(x1, W1, b1, h,
                                                          NTOK, 4096, 1024);
    // 4) ffn = h @ W2 + b2              (16384x4096 @ 4096x1024)
    gemm_kernel<0><<<dim3(1024 / 128, NTOK / 128), 256>>>(h, W2, b2, ffn,
                                                          NTOK, 1024, 4096);
    // 5) out = LN(x1 + ffn)
    resid_ln_kernel<<<NTOK, 256>>>(x1, ffn, g2, be2, out);
}

// round 4
// speedup vs baseline: 2.5378x; 2.5378x over previous
#include <cuda_runtime.h>
#include <math.h>
#include <stdint.h>

#define NTOK 16384            // B*S = 4*4096
#define DMODEL 1024

// Scratch (allocation-free rule: __device__ globals).
__device__ float g_big[(size_t)NTOK * 4096];   // qkv (stages 1-2) then h (3-4)
__device__ float g_x1 [(size_t)NTOK * 1024];   // post-attention LN out
__device__ float g_ffn[(size_t)NTOK * 1024];   // ffn_out

// ---------------------------------------------------------------------------
__device__ __forceinline__ uint32_t f2tf32(float x) {
    uint32_t r;
    asm("cvt.rna.tf32.f32 %0, %1;" : "=r"(r) : "r"(__float_as_uint(x)));
    return r;
}

__device__ __forceinline__ void mma_tf32(float4& c,
    uint32_t a0, uint32_t a1, uint32_t a2, uint32_t a3,
    uint32_t b0, uint32_t b1)
{
    asm volatile(
        "mma.sync.aligned.m16n8k8.row.col.f32.tf32.tf32.f32 "
        "{%0,%1,%2,%3}, {%4,%5,%6,%7}, {%8,%9}, {%0,%1,%2,%3};"
        : "+f"(c.x), "+f"(c.y), "+f"(c.z), "+f"(c.w)
        : "r"(a0), "r"(a1), "r"(a2), "r"(a3), "r"(b0), "r"(b1));
}

// ---------------------------------------------------------------------------
// tf32 tensor-core GEMM: C[M,N] = A[M,K] @ B[K,N] + bias[N], optional GELU.
// BM=BN=128, BK=32, 256 threads (8 warps), warp tile 64x32 via m16n8k8.
// A smem: M-major, stride 36 (conflict-free fragment loads).
// B smem: K-major, stride 128, XOR swizzle n^(8*(k&3)) (conflict-free).
// Register double-buffer over single smem buffer; cvt.rna tf32 on the fill.
// ---------------------------------------------------------------------------
template<int EPI>   // 0 = bias, 1 = bias + gelu(exact)
__global__ __launch_bounds__(256) void gemm_tf32_kernel(
    const float* __restrict__ A, const float* __restrict__ B,
    const float* __restrict__ bias, float* __restrict__ C,
    int M, int N, int K)
{
    constexpr int BK = 32;
    __shared__ float As[128][36];    // [m][k], stride 36
    __shared__ float Bs[32][128];    // [k][n^swz]

    const int tid  = threadIdx.x;
    const int lane = tid & 31;
    const int wid  = tid >> 5;
    const int gid  = lane >> 2;      // 0..7
    const int tig  = lane & 3;       // 0..3

    const int wm = wid & 1;          // 2 warp-rows  x 64
    const int wn = wid >> 1;         // 4 warp-cols  x 32
    const int bm = blockIdx.y * 128;
    const int bn = blockIdx.x * 128;

    // loader indices
    const int am  = tid >> 1;        // A row 0..127
    const int akh = tid & 1;         // k half (0/1) -> 16 floats each
    const int bkr = tid >> 3;        // B row 0..31
    const int bcg = tid & 7;         // B col group

    const float* Ag = A + (size_t)(bm + am) * K + akh * 16;
    const float* Bg = B + (size_t)bkr * N + bn;

    float4 c[4][4];
    #pragma unroll
    for (int i = 0; i < 4; i++)
        #pragma unroll
        for (int j = 0; j < 4; j++) c[i][j] = make_float4(0.f, 0.f, 0.f, 0.f);

    const int NT = K / BK;
    float4 fa[4], fb[4];

    // ---- prologue: fetch tile 0 ----
    #pragma unroll
    for (int i = 0; i < 4; i++) {
        fa[i] = *(const float4*)(Ag + i * 4);
        fb[i] = *(const float4*)(Bg + (bcg + 8 * i) * 4);
    }
    #pragma unroll
    for (int i = 0; i < 4; i++) {
        float4 t;
        t.x = __uint_as_float(f2tf32(fa[i].x)); t.y = __uint_as_float(f2tf32(fa[i].y));
        t.z = __uint_as_float(f2tf32(fa[i].z)); t.w = __uint_as_float(f2tf32(fa[i].w));
        *(float4*)&As[am][akh * 16 + i * 4] = t;
        float4 u;
        u.x = __uint_as_float(f2tf32(fb[i].x)); u.y = __uint_as_float(f2tf32(fb[i].y));
        u.z = __uint_as_float(f2tf32(fb[i].z)); u.w = __uint_as_float(f2tf32(fb[i].w));
        *(float4*)&Bs[bkr][((bcg + 8 * i) * 4) ^ (8 * (bkr & 3))] = u;
    }
    __syncthreads();

    for (int kt = 0; kt < NT; kt++) {
        // ---- prefetch next tile into registers (overlaps MMA loop) ----
        if (kt + 1 < NT) {
            const float* Ag2 = Ag + (kt + 1) * BK;
            const float* Bg2 = Bg + (size_t)(kt + 1) * BK * N;
            #pragma unroll
            for (int i = 0; i < 4; i++) {
                fa[i] = *(const float4*)(Ag2 + i * 4);
                fb[i] = *(const float4*)(Bg2 + (bcg + 8 * i) * 4);
            }
        }

        // ---- MMA over 4 k-steps ----
        #pragma unroll
        for (int ks = 0; ks < 4; ks++) {
            const int k0 = ks * 8;
            uint32_t a[4][4], b[4][2];
            #pragma unroll
            for (int i = 0; i < 4; i++) {
                const int m0 = wm * 64 + 16 * i + gid;
                a[i][0] = __float_as_uint(As[m0    ][k0 + tig    ]);
                a[i][1] = __float_as_uint(As[m0 + 8][k0 + tig    ]);
                a[i][2] = __float_as_uint(As[m0    ][k0 + tig + 4]);
                a[i][3] = __float_as_uint(As[m0 + 8][k0 + tig + 4]);
            }
            #pragma unroll
            for (int j = 0; j < 4; j++) {
                const int n0 = wn * 32 + 8 * j + gid;
                b[j][0] = __float_as_uint(Bs[k0 + tig    ][n0 ^ (8 * tig)]);
                b[j][1] = __float_as_uint(Bs[k0 + tig + 4][n0 ^ (8 * tig)]);
            }
            #pragma unroll
            for (int i = 0; i < 4; i++)
                #pragma unroll
                for (int j = 0; j < 4; j++)
                    mma_tf32(c[i][j], a[i][0], a[i][1], a[i][2], a[i][3],
                             b[j][0], b[j][1]);
        }

        // ---- store prefetched tile ----
        if (kt + 1 < NT) {
            __syncthreads();
            #pragma unroll
            for (int i = 0; i < 4; i++) {
                float4 t;
                t.x = __uint_as_float(f2tf32(fa[i].x)); t.y = __uint_as_float(f2tf32(fa[i].y));
                t.z = __uint_as_float(f2tf32(fa[i].z)); t.w = __uint_as_float(f2tf32(fa[i].w));
                *(float4*)&As[am][akh * 16 + i * 4] = t;
                float4 u;
                u.x = __uint_as_float(f2tf32(fb[i].x)); u.y = __uint_as_float(f2tf32(fb[i].y));
                u.z = __uint_as_float(f2tf32(fb[i].z)); u.w = __uint_as_float(f2tf32(fb[i].w));
                *(float4*)&Bs[bkr][((bcg + 8 * i) * 4) ^ (8 * (bkr & 3))] = u;
            }
            __syncthreads();
        }
    }

    // ---- epilogue: bias (+gelu), float2 stores ----
    #pragma unroll
    for (int i = 0; i < 4; i++) {
        const int row0 = bm + wm * 64 + 16 * i + gid;
        #pragma unroll
        for (int j = 0; j < 4; j++) {
            const int col = bn + wn * 32 + 8 * j + 2 * tig;
            const float bz0 = bias[col], bz1 = bias[col + 1];
            float v0 = c[i][j].x + bz0, v1 = c[i][j].y + bz1;
            float v2 = c[i][j].z + bz0, v3 = c[i][j].w + bz1;
            if (EPI == 1) {
                v0 = 0.5f * v0 * (1.0f + erff(v0 * 0.7071067811865476f));
                v1 = 0.5f * v1 * (1.0f + erff(v1 * 0.7071067811865476f));
                v2 = 0.5f * v2 * (1.0f + erff(v2 * 0.7071067811865476f));
                v3 = 0.5f * v3 * (1.0f + erff(v3 * 0.7071067811865476f));
            }
            *(float2*)(C + (size_t)row0 * N + col)       = make_float2(v0, v1);
            *(float2*)(C + (size_t)(row0 + 8) * N + col) = make_float2(v2, v3);
        }
    }
}

// ---------------------------------------------------------------------------
// Fused per-token head-mix "attention" + residual + LayerNorm (unchanged).
// ---------------------------------------------------------------------------
__global__ __launch_bounds__(256) void attn_ln_kernel(
    const float* __restrict__ qkv, const float* __restrict__ x,
    const float* __restrict__ g1, const float* __restrict__ beta1,
    float* __restrict__ x1)
{
    __shared__ float sPad[3 * 16 * 65];
    __shared__ float sP[256];
    __shared__ float wred[16];

    const int token = blockIdx.x;
    const int tid = threadIdx.x;
    const float* row = qkv + (size_t)token * 3072;

    for (int i = tid; i < 3072; i += 256) {
        int sec = i >> 10, r = (i & 1023) >> 6, d = i & 63;
        sPad[sec * 1040 + r * 65 + d] = row[i];
    }
    __syncthreads();

    const float* sQ = sPad;
    const float* sK = sPad + 1040;
    const float* sV = sPad + 2080;

    const int h = tid >> 4, g = tid & 15;
    float s = 0.f;
    #pragma unroll
    for (int d = 0; d < 64; d++) s += sQ[h * 65 + d] * sK[g * 65 + d];
    sP[tid] = s * 0.125f;
    __syncthreads();

    float rv[16];
    #pragma unroll
    for (int j = 0; j < 16; j++) rv[j] = sP[h * 16 + j];
    float mx = rv[0];
    #pragma unroll
    for (int j = 1; j < 16; j++) mx = fmaxf(mx, rv[j]);
    float sum = 0.f;
    #pragma unroll
    for (int j = 0; j < 16; j++) sum += __expf(rv[j] - mx);
    float attn = __expf(rv[g] - mx) / sum;
    __syncthreads();
    sP[tid] = attn;
    __syncthreads();

    const float* xr = x + (size_t)token * 1024;
    float y[4];
    #pragma unroll
    for (int i = 0; i < 4; i++) {
        int idx = tid + i * 256;
        int hh = idx >> 6, d = idx & 63;
        float a = 0.f;
        #pragma unroll
        for (int gg = 0; gg < 16; gg++) a += sP[hh * 16 + gg] * sV[gg * 65 + d];
        y[i] = a + xr[idx];
    }

    float lsum = y[0] + y[1] + y[2] + y[3];
    float lsq  = y[0]*y[0] + y[1]*y[1] + y[2]*y[2] + y[3]*y[3];
    #pragma unroll
    for (int o = 16; o > 0; o >>= 1) {
        lsum += __shfl_down_sync(0xffffffffu, lsum, o);
        lsq  += __shfl_down_sync(0xffffffffu, lsq,  o);
    }
    const int wid = tid >> 5, lane = tid & 31;
    if (lane == 0) { wred[wid] = lsum; wred[8 + wid] = lsq; }
    __syncthreads();
    float tot = 0.f, totsq = 0.f;
    #pragma unroll
    for (int i = 0; i < 8; i++) { tot += wred[i]; totsq += wred[8 + i]; }
    float mu  = tot * (1.0f / 1024.0f);
    float var = totsq * (1.0f / 1024.0f) - mu * mu;
    float inv = rsqrtf(var + 1e-5f);

    float* o = x1 + (size_t)token * 1024;
    #pragma unroll
    for (int i = 0; i < 4; i++) {
        int idx = tid + i * 256;
        o[idx] = (y[i] - mu) * inv * g1[idx] + beta1[idx];
    }
}

// ---------------------------------------------------------------------------
__global__ __launch_bounds__(256) void resid_ln_kernel(
    const float* __restrict__ a, const float* __restrict__ b,
    const float* __restrict__ g, const float* __restrict__ beta,
    float* __restrict__ out)
{
    __shared__ float wred[16];
    const int token = blockIdx.x;
    const int tid = threadIdx.x;
    const float* ar = a + (size_t)token * 1024;
    const float* br = b + (size_t)token * 1024;

    float y[4];
    #pragma unroll
    for (int i = 0; i < 4; i++) {
        int idx = tid + i * 256;
        y[i] = ar[idx] + br[idx];
    }
    float lsum = y[0] + y[1] + y[2] + y[3];
    float lsq  = y[0]*y[0] + y[1]*y[1] + y[2]*y[2] + y[3]*y[3];
    #pragma unroll
    for (int o = 16; o > 0; o >>= 1) {
        lsum += __shfl_down_sync(0xffffffffu, lsum, o);
        lsq  += __shfl_down_sync(0xffffffffu, lsq,  o);
    }
    const int wid = tid >> 5, lane = tid & 31;
    if (lane == 0) { wred[wid] = lsum; wred[8 + wid] = lsq; }
    __syncthreads();
    float tot = 0.f, totsq = 0.f;
    #pragma unroll
    for (int i = 0; i < 8; i++) { tot += wred[i]; totsq += wred[8 + i]; }
    float mu  = tot * (1.0f / 1024.0f);
    float var = totsq * (1.0f / 1024.0f) - mu * mu;
    float inv = rsqrtf(var + 1e-5f);

    float* o = out + (size_t)token * 1024;
    #pragma unroll
    for (int i = 0; i < 4; i++) {
        int idx = tid + i * 256;
        o[idx] = (y[i] - mu) * inv * g[idx] + beta[idx];
    }
}

// ---------------------------------------------------------------------------
extern "C" void kernel_launch(void* const* d_in, const int* in_sizes, int n_in,
                              void* d_out, int out_size)
{
    const float* x    = (const float*)d_in[0];
    const float* Wqkv = (const float*)d_in[1];
    const float* bqkv = (const float*)d_in[2];
    const float* W1   = (const float*)d_in[3];
    const float* b1   = (const float*)d_in[4];
    const float* W2   = (const float*)d_in[5];
    const float* b2   = (const float*)d_in[6];
    const float* g1   = (const float*)d_in[7];
    const float* be1  = (const float*)d_in[8];
    const float* g2   = (const float*)d_in[9];
    const float* be2  = (const float*)d_in[10];
    float* out = (float*)d_out;

    float *big, *x1, *ffn;
    cudaGetSymbolAddress((void**)&big, g_big);
    cudaGetSymbolAddress((void**)&x1,  g_x1);
    cudaGetSymbolAddress((void**)&ffn, g_ffn);
    float* qkv = big;   // stages 1-2
    float* h   = big;   // stages 3-4 (qkv dead after stage 2)

    // 1) qkv = x @ Wqkv + bqkv          (16384x1024 @ 1024x3072)
    gemm_tf32_kernel<0><<<dim3(3072 / 128, NTOK / 128), 256>>>(x, Wqkv, bqkv, qkv,
                                                               NTOK, 3072, 1024);
    // 2) x1 = LN(x + headmix(qkv))
    attn_ln_kernel<<<NTOK, 256>>>(qkv, x, g1, be1, x1);
    // 3) h = gelu(x1 @ W1 + b1)         (16384x1024 @ 1024x4096)
    gemm_tf32_kernel<1><<<dim3(4096 / 128, NTOK / 128), 256>>>(x1, W1, b1, h,
                                                               NTOK, 4096, 1024);
    // 4) ffn = h @ W2 + b2              (16384x4096 @ 4096x1024)
    gemm_tf32_kernel<0><<<dim3(1024 / 128, NTOK / 128), 256>>>(h, W2, b2, ffn,
                                                               NTOK, 1024, 4096);
    // 5) out = LN(x1 + ffn)
    resid_ln_kernel<<<NTOK, 256>>>(x1, ffn, g2, be2, out);
}

// round 6
// speedup vs baseline: 2.9405x; 1.1587x over previous
#include <cuda_runtime.h>
#include <math.h>
#include <stdint.h>

#define NTOK 16384            // B*S
#define DM   1024

// ---------------- device scratch (allocation-free rule) ----------------
__device__ float g_qkv[(size_t)NTOK * 3072];
__device__ float g_x1 [(size_t)NTOK * DM];
__device__ float g_ffn[(size_t)NTOK * DM];
__device__ float g_xc [(size_t)NTOK * DM];      // x rounded to tf32
__device__ float g_x1c[(size_t)NTOK * DM];      // x1 rounded to tf32
__device__ float g_h  [(size_t)NTOK * 4096];    // gelu hidden (tf32-rounded)
__device__ float g_wqt[3072 * 1024];            // Wqkv^T, tf32
__device__ float g_w1t[4096 * 1024];            // W1^T, tf32
__device__ float g_w2t[1024 * 4096];            // W2^T, tf32

// ---------------- PTX helpers (baseline ISA only; no 'a' features) -------
__device__ __forceinline__ uint32_t f2tf32(float x) {
    uint32_t r;
    asm("cvt.rna.tf32.f32 %0, %1;" : "=r"(r) : "r"(__float_as_uint(x)));
    return r;
}
__device__ __forceinline__ uint32_t smem_u32(const void* p) {
    uint32_t a;
    asm("{ .reg .u64 t; cvta.to.shared.u64 t, %1; cvt.u32.u64 %0, t; }"
        : "=r"(a) : "l"(p));
    return a;
}
__device__ __forceinline__ void cp16(uint32_t dst, const void* src) {
    asm volatile("cp.async.cg.shared.global [%0], [%1], 16;"
                 :: "r"(dst), "l"(src));
}
#define CP_COMMIT() asm volatile("cp.async.commit_group;" ::: "memory")
#define CP_WAIT(n)  asm volatile("cp.async.wait_group %0;" :: "n"(n) : "memory")

__device__ __forceinline__ void ldsm4(uint32_t& r0, uint32_t& r1,
                                      uint32_t& r2, uint32_t& r3, uint32_t addr) {
    asm volatile("ldmatrix.sync.aligned.m8n8.x4.shared.b16 {%0,%1,%2,%3}, [%4];"
                 : "=r"(r0), "=r"(r1), "=r"(r2), "=r"(r3) : "r"(addr));
}
__device__ __forceinline__ void mma_tf32(float4& c,
    uint32_t a0, uint32_t a1, uint32_t a2, uint32_t a3,
    uint32_t b0, uint32_t b1)
{
    asm volatile(
        "mma.sync.aligned.m16n8k8.row.col.f32.tf32.tf32.f32 "
        "{%0,%1,%2,%3}, {%4,%5,%6,%7}, {%8,%9}, {%0,%1,%2,%3};"
        : "+f"(c.x), "+f"(c.y), "+f"(c.z), "+f"(c.w)
        : "r"(a0), "r"(a1), "r"(a2), "r"(a3), "r"(b0), "r"(b1));
}

// ---------------- tf32 mma GEMM, ldmatrix + cp.async ----------------
// C[M,N] = A[M,K] @ Bt[N,K]^T + bias.  A, Bt pre-rounded to tf32.
// Tile 128x128xBK32, 256 thr (8 warps), warp 64x32, 2-stage cp.async pipe.
// Smem per tile: 128 rows x 36 floats (stride 36 -> 144B rows, ldmatrix
// phases conflict-free).
static constexpr int TILE_B  = 128 * 36 * 4;          // 18432
static constexpr int STAGE_B = 2 * TILE_B;            // A + B
static constexpr int GSMEM   = 2 * STAGE_B;           // 73728

template<int EPI, int TFOUT>   // EPI: exact gelu; TFOUT: round store to tf32
__global__ __launch_bounds__(256, 2) void gemm_mma_kernel(
    const float* __restrict__ A, const float* __restrict__ Bt,
    const float* __restrict__ bias, float* __restrict__ C,
    int M, int N, int K)
{
    extern __shared__ float dsm[];
    const uint32_t sbase = smem_u32(dsm);

    const int tid  = threadIdx.x;
    const int lane = tid & 31;
    const int wid  = tid >> 5;
    const int gid  = lane >> 2, tig = lane & 3;
    const int wm = wid & 1, wn = wid >> 1;
    const int bm = blockIdx.y * 128, bn = blockIdx.x * 128;

    // fill indices: each thread 4+4 cp.async of 16B
    const int frow = tid >> 1, fhalf = tid & 1;
    const float* agp = A  + (size_t)(bm + frow) * K + fhalf * 16;
    const float* bgp = Bt + (size_t)(bn + frow) * K + fhalf * 16;
    const uint32_t foff = (frow * 36 + fhalf * 16) * 4;

    // ldmatrix per-lane addresses
    const int rs = lane & 7, mt = lane >> 3;
    const uint32_t aoff = ((wm * 64 + (mt & 1) * 8 + rs) * 36 + (mt >> 1) * 4) * 4;
    const uint32_t boff = ((wn * 32 + (mt >> 1) * 8 + rs) * 36 + (mt & 1) * 4) * 4;

    float4 c[4][4];
    #pragma unroll
    for (int i = 0; i < 4; i++)
        #pragma unroll
        for (int j = 0; j < 4; j++) c[i][j] = make_float4(0.f, 0.f, 0.f, 0.f);

    const int NT = K >> 5;

    // prologue: stage 0
    {
        const uint32_t dA = sbase + foff, dB = sbase + TILE_B + foff;
        #pragma unroll
        for (int i = 0; i < 4; i++) {
            cp16(dA + i * 16, agp + i * 4);
            cp16(dB + i * 16, bgp + i * 4);
        }
        CP_COMMIT();
    }

    for (int kt = 0; kt < NT; kt++) {
        if (kt + 1 < NT) {
            const int k0 = (kt + 1) << 5;
            const uint32_t sb = sbase + ((kt + 1) & 1) * STAGE_B;
            const uint32_t dA = sb + foff, dB = sb + TILE_B + foff;
            #pragma unroll
            for (int i = 0; i < 4; i++) {
                cp16(dA + i * 16, agp + k0 + i * 4);
                cp16(dB + i * 16, bgp + k0 + i * 4);
            }
            CP_COMMIT();
            CP_WAIT(1);
        } else {
            CP_WAIT(0);
        }
        __syncthreads();

        const uint32_t sA = sbase + (kt & 1) * STAGE_B;
        const uint32_t sB = sA + TILE_B;
        #pragma unroll
        for (int ks = 0; ks < 4; ks++) {
            const uint32_t kb = ks * 32;
            uint32_t a[4][4], b[2][4];
            #pragma unroll
            for (int i = 0; i < 4; i++)
                ldsm4(a[i][0], a[i][1], a[i][2], a[i][3],
                      sA + aoff + i * 2304 + kb);
            #pragma unroll
            for (int j2 = 0; j2 < 2; j2++)
                ldsm4(b[j2][0], b[j2][1], b[j2][2], b[j2][3],
                      sB + boff + j2 * 2304 + kb);
            #pragma unroll
            for (int i = 0; i < 4; i++)
                #pragma unroll
                for (int j = 0; j < 4; j++)
                    mma_tf32(c[i][j], a[i][0], a[i][1], a[i][2], a[i][3],
                             b[j >> 1][(j & 1) * 2], b[j >> 1][(j & 1) * 2 + 1]);
        }
        __syncthreads();
    }

    // epilogue: bias (+gelu) (+tf32 round), float2 stores from registers
    #pragma unroll
    for (int i = 0; i < 4; i++) {
        const int row0 = bm + wm * 64 + 16 * i + gid;
        #pragma unroll
        for (int j = 0; j < 4; j++) {
            const int col = bn + wn * 32 + 8 * j + 2 * tig;
            const float bz0 = bias[col], bz1 = bias[col + 1];
            float v0 = c[i][j].x + bz0, v1 = c[i][j].y + bz1;
            float v2 = c[i][j].z + bz0, v3 = c[i][j].w + bz1;
            if (EPI == 1) {
                v0 = 0.5f * v0 * (1.0f + erff(v0 * 0.7071067811865476f));
                v1 = 0.5f * v1 * (1.0f + erff(v1 * 0.7071067811865476f));
                v2 = 0.5f * v2 * (1.0f + erff(v2 * 0.7071067811865476f));
                v3 = 0.5f * v3 * (1.0f + erff(v3 * 0.7071067811865476f));
            }
            if (TFOUT == 1) {
                v0 = __uint_as_float(f2tf32(v0)); v1 = __uint_as_float(f2tf32(v1));
                v2 = __uint_as_float(f2tf32(v2)); v3 = __uint_as_float(f2tf32(v3));
            }
            *(float2*)(C + (size_t)row0 * N + col)       = make_float2(v0, v1);
            *(float2*)(C + (size_t)(row0 + 8) * N + col) = make_float2(v2, v3);
        }
    }
}

// ---------------- converts ----------------
__global__ __launch_bounds__(256) void round_tf32_kernel(
    const float* __restrict__ src, float* __restrict__ dst, size_t n4)
{
    size_t i = (size_t)blockIdx.x * 256 + threadIdx.x;
    if (i >= n4) return;
    float4 v = *(const float4*)(src + i * 4);
    v.x = __uint_as_float(f2tf32(v.x)); v.y = __uint_as_float(f2tf32(v.y));
    v.z = __uint_as_float(f2tf32(v.z)); v.w = __uint_as_float(f2tf32(v.w));
    *(float4*)(dst + i * 4) = v;
}

// W[K][N] fp32 -> Wt[N][K] tf32-rounded fp32
__global__ __launch_bounds__(256) void transpose_tf32_kernel(
    const float* __restrict__ W, float* __restrict__ T, int Kd, int Nd)
{
    __shared__ float t[32][33];
    const int n0 = blockIdx.x * 32, k0 = blockIdx.y * 32;
    const int tx = threadIdx.x, ty = threadIdx.y;
    #pragma unroll
    for (int j = 0; j < 4; j++)
        t[ty + 8 * j][tx] = W[(size_t)(k0 + ty + 8 * j) * Nd + n0 + tx];
    __syncthreads();
    #pragma unroll
    for (int j = 0; j < 4; j++) {
        float v = t[tx][ty + 8 * j];
        T[(size_t)(n0 + ty + 8 * j) * Kd + k0 + tx] = __uint_as_float(f2tf32(v));
    }
}

// ---------------- fused head-mix attention + residual + LN ----------------
__global__ __launch_bounds__(256) void attn_ln_kernel(
    const float* __restrict__ qkv, const float* __restrict__ x,
    const float* __restrict__ g1, const float* __restrict__ beta1,
    float* __restrict__ x1, float* __restrict__ x1c)
{
    __shared__ float sPad[3 * 16 * 65];
    __shared__ float sP[256];
    __shared__ float wred[16];

    const int token = blockIdx.x;
    const int tid = threadIdx.x;
    const float* row = qkv + (size_t)token * 3072;

    for (int i = tid; i < 3072; i += 256) {
        int sec = i >> 10, r = (i & 1023) >> 6, d = i & 63;
        sPad[sec * 1040 + r * 65 + d] = row[i];
    }
    __syncthreads();

    const float* sQ = sPad;
    const float* sK = sPad + 1040;
    const float* sV = sPad + 2080;

    const int h = tid >> 4, g = tid & 15;
    float s = 0.f;
    #pragma unroll
    for (int d = 0; d < 64; d++) s += sQ[h * 65 + d] * sK[g * 65 + d];
    sP[tid] = s * 0.125f;
    __syncthreads();

    float rv[16];
    #pragma unroll
    for (int j = 0; j < 16; j++) rv[j] = sP[h * 16 + j];
    float mx = rv[0];
    #pragma unroll
    for (int j = 1; j < 16; j++) mx = fmaxf(mx, rv[j]);
    float sum = 0.f;
    #pragma unroll
    for (int j = 0; j < 16; j++) sum += __expf(rv[j] - mx);
    float attn = __expf(rv[g] - mx) / sum;
    __syncthreads();
    sP[tid] = attn;
    __syncthreads();

    const float* xr = x + (size_t)token * 1024;
    float y[4];
    #pragma unroll
    for (int i = 0; i < 4; i++) {
        int idx = tid + i * 256;
        int hh = idx >> 6, d = idx & 63;
        float a = 0.f;
        #pragma unroll
        for (int gg = 0; gg < 16; gg++) a += sP[hh * 16 + gg] * sV[gg * 65 + d];
        y[i] = a + xr[idx];
    }

    float lsum = y[0] + y[1] + y[2] + y[3];
    float lsq  = y[0]*y[0] + y[1]*y[1] + y[2]*y[2] + y[3]*y[3];
    #pragma unroll
    for (int o = 16; o > 0; o >>= 1) {
        lsum += __shfl_down_sync(0xffffffffu, lsum, o);
        lsq  += __shfl_down_sync(0xffffffffu, lsq,  o);
    }
    const int wid = tid >> 5, lane = tid & 31;
    if (lane == 0) { wred[wid] = lsum; wred[8 + wid] = lsq; }
    __syncthreads();
    float tot = 0.f, totsq = 0.f;
    #pragma unroll
    for (int i = 0; i < 8; i++) { tot += wred[i]; totsq += wred[8 + i]; }
    float mu  = tot * (1.0f / 1024.0f);
    float var = totsq * (1.0f / 1024.0f) - mu * mu;
    float inv = rsqrtf(var + 1e-5f);

    #pragma unroll
    for (int i = 0; i < 4; i++) {
        int idx = tid + i * 256;
        float v = (y[i] - mu) * inv * g1[idx] + beta1[idx];
        size_t o = (size_t)token * 1024 + idx;
        x1[o]  = v;
        x1c[o] = __uint_as_float(f2tf32(v));
    }
}

// ---------------- final residual + LN ----------------
__global__ __launch_bounds__(256) void resid_ln_kernel(
    const float* __restrict__ a, const float* __restrict__ b,
    const float* __restrict__ g, const float* __restrict__ beta,
    float* __restrict__ out)
{
    __shared__ float wred[16];
    const int token = blockIdx.x;
    const int tid = threadIdx.x;
    const float* ar = a + (size_t)token * 1024;
    const float* br = b + (size_t)token * 1024;

    float y[4];
    #pragma unroll
    for (int i = 0; i < 4; i++) {
        int idx = tid + i * 256;
        y[i] = ar[idx] + br[idx];
    }
    float lsum = y[0] + y[1] + y[2] + y[3];
    float lsq  = y[0]*y[0] + y[1]*y[1] + y[2]*y[2] + y[3]*y[3];
    #pragma unroll
    for (int o = 16; o > 0; o >>= 1) {
        lsum += __shfl_down_sync(0xffffffffu, lsum, o);
        lsq  += __shfl_down_sync(0xffffffffu, lsq,  o);
    }
    const int wid = tid >> 5, lane = tid & 31;
    if (lane == 0) { wred[wid] = lsum; wred[8 + wid] = lsq; }
    __syncthreads();
    float tot = 0.f, totsq = 0.f;
    #pragma unroll
    for (int i = 0; i < 8; i++) { tot += wred[i]; totsq += wred[8 + i]; }
    float mu  = tot * (1.0f / 1024.0f);
    float var = totsq * (1.0f / 1024.0f) - mu * mu;
    float inv = rsqrtf(var + 1e-5f);

    float* o = out + (size_t)token * 1024;
    #pragma unroll
    for (int i = 0; i < 4; i++) {
        int idx = tid + i * 256;
        o[idx] = (y[i] - mu) * inv * g[idx] + beta[idx];
    }
}

// ---------------------------------------------------------------------------
extern "C" void kernel_launch(void* const* d_in, const int* in_sizes, int n_in,
                              void* d_out, int out_size)
{
    const float* x    = (const float*)d_in[0];
    const float* Wqkv = (const float*)d_in[1];
    const float* bqkv = (const float*)d_in[2];
    const float* W1   = (const float*)d_in[3];
    const float* b1   = (const float*)d_in[4];
    const float* W2   = (const float*)d_in[5];
    const float* b2   = (const float*)d_in[6];
    const float* g1   = (const float*)d_in[7];
    const float* be1  = (const float*)d_in[8];
    const float* g2   = (const float*)d_in[9];
    const float* be2  = (const float*)d_in[10];
    float* out = (float*)d_out;

    float *qkv, *x1, *ffn, *xc, *x1c, *h, *wqt, *w1t, *w2t;
    cudaGetSymbolAddress((void**)&qkv, g_qkv);
    cudaGetSymbolAddress((void**)&x1,  g_x1);
    cudaGetSymbolAddress((void**)&ffn, g_ffn);
    cudaGetSymbolAddress((void**)&xc,  g_xc);
    cudaGetSymbolAddress((void**)&x1c, g_x1c);
    cudaGetSymbolAddress((void**)&h,   g_h);
    cudaGetSymbolAddress((void**)&wqt, g_wqt);
    cudaGetSymbolAddress((void**)&w1t, g_w1t);
    cudaGetSymbolAddress((void**)&w2t, g_w2t);

    cudaFuncSetAttribute(gemm_mma_kernel<0,0>,
                         cudaFuncAttributeMaxDynamicSharedMemorySize, GSMEM);
    cudaFuncSetAttribute(gemm_mma_kernel<1,1>,
                         cudaFuncAttributeMaxDynamicSharedMemorySize, GSMEM);

    // one-time converts (tf32 rounding + weight transposes)
    round_tf32_kernel<<<(NTOK * DM / 4 + 255) / 256, 256>>>(x, xc,
                                                            (size_t)NTOK * DM / 4);
    transpose_tf32_kernel<<<dim3(3072 / 32, 1024 / 32), dim3(32, 8)>>>(Wqkv, wqt, 1024, 3072);
    transpose_tf32_kernel<<<dim3(4096 / 32, 1024 / 32), dim3(32, 8)>>>(W1,   w1t, 1024, 4096);
    transpose_tf32_kernel<<<dim3(1024 / 32, 4096 / 32), dim3(32, 8)>>>(W2,   w2t, 4096, 1024);

    // 1) qkv = x @ Wqkv + bqkv
    gemm_mma_kernel<0,0><<<dim3(3072 / 128, NTOK / 128), 256, GSMEM>>>(
        xc, wqt, bqkv, qkv, NTOK, 3072, 1024);
    // 2) x1 = LN(x + headmix(qkv)); also emit tf32-rounded copy
    attn_ln_kernel<<<NTOK, 256>>>(qkv, x, g1, be1, x1, x1c);
    // 3) h = gelu(x1 @ W1 + b1), tf32-rounded out
    gemm_mma_kernel<1,1><<<dim3(4096 / 128, NTOK / 128), 256, GSMEM>>>(
        x1c, w1t, b1, h, NTOK, 4096, 1024);
    // 4) ffn = h @ W2 + b2
    gemm_mma_kernel<0,0><<<dim3(1024 / 128, NTOK / 128), 256, GSMEM>>>(
        h, w2t, b2, ffn, NTOK, 1024, 4096);
    // 5) out = LN(x1 + ffn)
    resid_ln_kernel<<<NTOK, 256>>>(x1, ffn, g2, be2, out);
}

// round 7
// speedup vs baseline: 3.6167x; 1.2300x over previous
#include <cuda_runtime.h>
#include <math.h>
#include <stdint.h>

#define NTOK 16384            // B*S
#define DM   1024

// ---------------- device scratch (allocation-free rule) ----------------
__device__ float g_qkv[(size_t)NTOK * 3072];
__device__ float g_x1 [(size_t)NTOK * DM];
__device__ float g_ffn[(size_t)NTOK * DM];
__device__ float g_xc [(size_t)NTOK * DM];      // x rounded to tf32
__device__ float g_x1c[(size_t)NTOK * DM];      // x1 rounded to tf32
__device__ float g_h  [(size_t)NTOK * 4096];    // gelu hidden (tf32-rounded)
__device__ float g_wqt[3072 * 1024];            // Wqkv^T, tf32
__device__ float g_w1t[4096 * 1024];            // W1^T, tf32
__device__ float g_w2t[1024 * 4096];            // W2^T, tf32

// ---------------- PTX helpers (baseline ISA only) ----------------
__device__ __forceinline__ uint32_t f2tf32(float x) {
    uint32_t r;
    asm("cvt.rna.tf32.f32 %0, %1;" : "=r"(r) : "r"(__float_as_uint(x)));
    return r;
}
__device__ __forceinline__ uint32_t smem_u32(const void* p) {
    uint32_t a;
    asm("{ .reg .u64 t; cvta.to.shared.u64 t, %1; cvt.u32.u64 %0, t; }"
        : "=r"(a) : "l"(p));
    return a;
}
__device__ __forceinline__ void cp16(uint32_t dst, const void* src) {
    asm volatile("cp.async.cg.shared.global [%0], [%1], 16;"
                 :: "r"(dst), "l"(src));
}
#define CP_COMMIT() asm volatile("cp.async.commit_group;" ::: "memory")
#define CP_WAIT(n)  asm volatile("cp.async.wait_group %0;" :: "n"(n) : "memory")

__device__ __forceinline__ void ldsm4(uint32_t& r0, uint32_t& r1,
                                      uint32_t& r2, uint32_t& r3, uint32_t addr) {
    asm volatile("ldmatrix.sync.aligned.m8n8.x4.shared.b16 {%0,%1,%2,%3}, [%4];"
                 : "=r"(r0), "=r"(r1), "=r"(r2), "=r"(r3) : "r"(addr));
}
__device__ __forceinline__ void mma_tf32(float4& c,
    uint32_t a0, uint32_t a1, uint32_t a2, uint32_t a3,
    uint32_t b0, uint32_t b1)
{
    asm volatile(
        "mma.sync.aligned.m16n8k8.row.col.f32.tf32.tf32.f32 "
        "{%0,%1,%2,%3}, {%4,%5,%6,%7}, {%8,%9}, {%0,%1,%2,%3};"
        : "+f"(c.x), "+f"(c.y), "+f"(c.z), "+f"(c.w)
        : "r"(a0), "r"(a1), "r"(a2), "r"(a3), "r"(b0), "r"(b1));
}

// ---------------- tf32 mma GEMM ----------------
// C[M,N] = A[M,K] @ Bt[N,K]^T + bias.  A, Bt pre-rounded to tf32.
// CTA tile 256x128xBK32, 256 thr (8 warps), warp tile 64x64 (4x2 warp grid),
// 2-stage cp.async pipeline. Rows padded to 36 floats (144B) -> ldmatrix
// phases conflict-free.
static constexpr int A_TILE_B = 256 * 36 * 4;         // 36864
static constexpr int B_TILE_B = 128 * 36 * 4;         // 18432
static constexpr int STAGE_B  = A_TILE_B + B_TILE_B;  // 55296
static constexpr int GSMEM    = 2 * STAGE_B;          // 110592

template<int EPI, int TFOUT>   // EPI: exact gelu; TFOUT: round store to tf32
__global__ __launch_bounds__(256, 1) void gemm_mma_kernel(
    const float* __restrict__ A, const float* __restrict__ Bt,
    const float* __restrict__ bias, float* __restrict__ C,
    int M, int N, int K)
{
    extern __shared__ float dsm[];
    const uint32_t sbase = smem_u32(dsm);

    const int tid  = threadIdx.x;
    const int lane = tid & 31;
    const int wid  = tid >> 5;
    const int gid  = lane >> 2, tig = lane & 3;
    const int wm = wid & 3;           // 4 warps over 256 rows (64 each)
    const int wn = wid >> 2;          // 2 warps over 128 cols (64 each)
    const int bm = blockIdx.y * 256, bn = blockIdx.x * 128;

    // fill indices: thread t covers row r0+32i (A, 8 iters) / r0+32i (B, 4),
    // chunk ch of 16B; warp = 4 consecutive rows x 128B contiguous.
    const int r0 = tid >> 3, ch = tid & 7;
    const float* agp = A  + (size_t)(bm + r0) * K + ch * 4;
    const float* bgp = Bt + (size_t)(bn + r0) * K + ch * 4;
    const uint32_t foff = (r0 * 36 + ch * 4) * 4;

    // ldmatrix per-lane addresses (row-pad 144B)
    const int rs = lane & 7, mt = lane >> 3;
    const uint32_t aoff = ((wm * 64 + (mt & 1) * 8 + rs) * 36 + (mt >> 1) * 4) * 4;
    const uint32_t boff = ((wn * 64 + (mt >> 1) * 8 + rs) * 36 + (mt & 1) * 4) * 4;

    float4 c[4][8];
    #pragma unroll
    for (int i = 0; i < 4; i++)
        #pragma unroll
        for (int j = 0; j < 8; j++) c[i][j] = make_float4(0.f, 0.f, 0.f, 0.f);

    const int NT = K >> 5;

    // prologue: stage 0
    {
        const uint32_t dA = sbase + foff, dB = sbase + A_TILE_B + foff;
        #pragma unroll
        for (int i = 0; i < 8; i++)
            cp16(dA + i * 32 * 144, agp + (size_t)i * 32 * K);
        #pragma unroll
        for (int i = 0; i < 4; i++)
            cp16(dB + i * 32 * 144, bgp + (size_t)i * 32 * K);
        CP_COMMIT();
    }

    for (int kt = 0; kt < NT; kt++) {
        if (kt + 1 < NT) {
            const int k0 = (kt + 1) << 5;
            const uint32_t sb = sbase + ((kt + 1) & 1) * STAGE_B;
            const uint32_t dA = sb + foff, dB = sb + A_TILE_B + foff;
            #pragma unroll
            for (int i = 0; i < 8; i++)
                cp16(dA + i * 32 * 144, agp + k0 + (size_t)i * 32 * K);
            #pragma unroll
            for (int i = 0; i < 4; i++)
                cp16(dB + i * 32 * 144, bgp + k0 + (size_t)i * 32 * K);
            CP_COMMIT();
            CP_WAIT(1);
        } else {
            CP_WAIT(0);
        }
        __syncthreads();

        const uint32_t sA = sbase + (kt & 1) * STAGE_B;
        const uint32_t sB = sA + A_TILE_B;
        #pragma unroll
        for (int ks = 0; ks < 4; ks++) {
            const uint32_t kb = ks * 32;
            uint32_t a[4][4], b[4][4];
            #pragma unroll
            for (int i = 0; i < 4; i++)
                ldsm4(a[i][0], a[i][1], a[i][2], a[i][3],
                      sA + aoff + i * 2304 + kb);
            #pragma unroll
            for (int j2 = 0; j2 < 4; j2++)
                ldsm4(b[j2][0], b[j2][1], b[j2][2], b[j2][3],
                      sB + boff + j2 * 2304 + kb);
            #pragma unroll
            for (int i = 0; i < 4; i++)
                #pragma unroll
                for (int j = 0; j < 8; j++)
                    mma_tf32(c[i][j], a[i][0], a[i][1], a[i][2], a[i][3],
                             b[j >> 1][(j & 1) * 2], b[j >> 1][(j & 1) * 2 + 1]);
        }
        __syncthreads();
    }

    // epilogue: bias (+gelu) (+tf32 round), float2 stores from registers
    #pragma unroll
    for (int i = 0; i < 4; i++) {
        const int row0 = bm + wm * 64 + 16 * i + gid;
        #pragma unroll
        for (int j = 0; j < 8; j++) {
            const int col = bn + wn * 64 + 8 * j + 2 * tig;
            const float bz0 = bias[col], bz1 = bias[col + 1];
            float v0 = c[i][j].x + bz0, v1 = c[i][j].y + bz1;
            float v2 = c[i][j].z + bz0, v3 = c[i][j].w + bz1;
            if (EPI == 1) {
                v0 = 0.5f * v0 * (1.0f + erff(v0 * 0.7071067811865476f));
                v1 = 0.5f * v1 * (1.0f + erff(v1 * 0.7071067811865476f));
                v2 = 0.5f * v2 * (1.0f + erff(v2 * 0.7071067811865476f));
                v3 = 0.5f * v3 * (1.0f + erff(v3 * 0.7071067811865476f));
            }
            if (TFOUT == 1) {
                v0 = __uint_as_float(f2tf32(v0)); v1 = __uint_as_float(f2tf32(v1));
                v2 = __uint_as_float(f2tf32(v2)); v3 = __uint_as_float(f2tf32(v3));
            }
            *(float2*)(C + (size_t)row0 * N + col)       = make_float2(v0, v1);
            *(float2*)(C + (size_t)(row0 + 8) * N + col) = make_float2(v2, v3);
        }
    }
}

// ---------------- converts ----------------
__global__ __launch_bounds__(256) void round_tf32_kernel(
    const float* __restrict__ src, float* __restrict__ dst, size_t n4)
{
    size_t i = (size_t)blockIdx.x * 256 + threadIdx.x;
    if (i >= n4) return;
    float4 v = *(const float4*)(src + i * 4);
    v.x = __uint_as_float(f2tf32(v.x)); v.y = __uint_as_float(f2tf32(v.y));
    v.z = __uint_as_float(f2tf32(v.z)); v.w = __uint_as_float(f2tf32(v.w));
    *(float4*)(dst + i * 4) = v;
}

// W[K][N] fp32 -> Wt[N][K] tf32-rounded fp32
__global__ __launch_bounds__(256) void transpose_tf32_kernel(
    const float* __restrict__ W, float* __restrict__ T, int Kd, int Nd)
{
    __shared__ float t[32][33];
    const int n0 = blockIdx.x * 32, k0 = blockIdx.y * 32;
    const int tx = threadIdx.x, ty = threadIdx.y;
    #pragma unroll
    for (int j = 0; j < 4; j++)
        t[ty + 8 * j][tx] = W[(size_t)(k0 + ty + 8 * j) * Nd + n0 + tx];
    __syncthreads();
    #pragma unroll
    for (int j = 0; j < 4; j++) {
        float v = t[tx][ty + 8 * j];
        T[(size_t)(n0 + ty + 8 * j) * Kd + k0 + tx] = __uint_as_float(f2tf32(v));
    }
}

// ---------------- fused head-mix attention + residual + LN ----------------
__global__ __launch_bounds__(256) void attn_ln_kernel(
    const float* __restrict__ qkv, const float* __restrict__ x,
    const float* __restrict__ g1, const float* __restrict__ beta1,
    float* __restrict__ x1, float* __restrict__ x1c)
{
    __shared__ float sPad[3 * 16 * 65];
    __shared__ float sP[256];
    __shared__ float wred[16];

    const int token = blockIdx.x;
    const int tid = threadIdx.x;
    const float* row = qkv + (size_t)token * 3072;

    for (int i = tid; i < 3072; i += 256) {
        int sec = i >> 10, r = (i & 1023) >> 6, d = i & 63;
        sPad[sec * 1040 + r * 65 + d] = row[i];
    }
    __syncthreads();

    const float* sQ = sPad;
    const float* sK = sPad + 1040;
    const float* sV = sPad + 2080;

    const int h = tid >> 4, g = tid & 15;
    float s = 0.f;
    #pragma unroll
    for (int d = 0; d < 64; d++) s += sQ[h * 65 + d] * sK[g * 65 + d];
    sP[tid] = s * 0.125f;
    __syncthreads();

    float rv[16];
    #pragma unroll
    for (int j = 0; j < 16; j++) rv[j] = sP[h * 16 + j];
    float mx = rv[0];
    #pragma unroll
    for (int j = 1; j < 16; j++) mx = fmaxf(mx, rv[j]);
    float sum = 0.f;
    #pragma unroll
    for (int j = 0; j < 16; j++) sum += __expf(rv[j] - mx);
    float attn = __expf(rv[g] - mx) / sum;
    __syncthreads();
    sP[tid] = attn;
    __syncthreads();

    const float* xr = x + (size_t)token * 1024;
    float y[4];
    #pragma unroll
    for (int i = 0; i < 4; i++) {
        int idx = tid + i * 256;
        int hh = idx >> 6, d = idx & 63;
        float a = 0.f;
        #pragma unroll
        for (int gg = 0; gg < 16; gg++) a += sP[hh * 16 + gg] * sV[gg * 65 + d];
        y[i] = a + xr[idx];
    }

    float lsum = y[0] + y[1] + y[2] + y[3];
    float lsq  = y[0]*y[0] + y[1]*y[1] + y[2]*y[2] + y[3]*y[3];
    #pragma unroll
    for (int o = 16; o > 0; o >>= 1) {
        lsum += __shfl_down_sync(0xffffffffu, lsum, o);
        lsq  += __shfl_down_sync(0xffffffffu, lsq,  o);
    }
    const int wid = tid >> 5, lane = tid & 31;
    if (lane == 0) { wred[wid] = lsum; wred[8 + wid] = lsq; }
    __syncthreads();
    float tot = 0.f, totsq = 0.f;
    #pragma unroll
    for (int i = 0; i < 8; i++) { tot += wred[i]; totsq += wred[8 + i]; }
    float mu  = tot * (1.0f / 1024.0f);
    float var = totsq * (1.0f / 1024.0f) - mu * mu;
    float inv = rsqrtf(var + 1e-5f);

    #pragma unroll
    for (int i = 0; i < 4; i++) {
        int idx = tid + i * 256;
        float v = (y[i] - mu) * inv * g1[idx] + beta1[idx];
        size_t o = (size_t)token * 1024 + idx;
        x1[o]  = v;
        x1c[o] = __uint_as_float(f2tf32(v));
    }
}

// ---------------- final residual + LN ----------------
__global__ __launch_bounds__(256) void resid_ln_kernel(
    const float* __restrict__ a, const float* __restrict__ b,
    const float* __restrict__ g, const float* __restrict__ beta,
    float* __restrict__ out)
{
    __shared__ float wred[16];
    const int token = blockIdx.x;
    const int tid = threadIdx.x;
    const float* ar = a + (size_t)token * 1024;
    const float* br = b + (size_t)token * 1024;

    float y[4];
    #pragma unroll
    for (int i = 0; i < 4; i++) {
        int idx = tid + i * 256;
        y[i] = ar[idx] + br[idx];
    }
    float lsum = y[0] + y[1] + y[2] + y[3];
    float lsq  = y[0]*y[0] + y[1]*y[1] + y[2]*y[2] + y[3]*y[3];
    #pragma unroll
    for (int o = 16; o > 0; o >>= 1) {
        lsum += __shfl_down_sync(0xffffffffu, lsum, o);
        lsq  += __shfl_down_sync(0xffffffffu, lsq,  o);
    }
    const int wid = tid >> 5, lane = tid & 31;
    if (lane == 0) { wred[wid] = lsum; wred[8 + wid] = lsq; }
    __syncthreads();
    float tot = 0.f, totsq = 0.f;
    #pragma unroll
    for (int i = 0; i < 8; i++) { tot += wred[i]; totsq += wred[8 + i]; }
    float mu  = tot * (1.0f / 1024.0f);
    float var = totsq * (1.0f / 1024.0f) - mu * mu;
    float inv = rsqrtf(var + 1e-5f);

    float* o = out + (size_t)token * 1024;
    #pragma unroll
    for (int i = 0; i < 4; i++) {
        int idx = tid + i * 256;
        o[idx] = (y[i] - mu) * inv * g[idx] + beta[idx];
    }
}

// ---------------------------------------------------------------------------
extern "C" void kernel_launch(void* const* d_in, const int* in_sizes, int n_in,
                              void* d_out, int out_size)
{
    const float* x    = (const float*)d_in[0];
    const float* Wqkv = (const float*)d_in[1];
    const float* bqkv = (const float*)d_in[2];
    const float* W1   = (const float*)d_in[3];
    const float* b1   = (const float*)d_in[4];
    const float* W2   = (const float*)d_in[5];
    const float* b2   = (const float*)d_in[6];
    const float* g1   = (const float*)d_in[7];
    const float* be1  = (const float*)d_in[8];
    const float* g2   = (const float*)d_in[9];
    const float* be2  = (const float*)d_in[10];
    float* out = (float*)d_out;

    float *qkv, *x1, *ffn, *xc, *x1c, *h, *wqt, *w1t, *w2t;
    cudaGetSymbolAddress((void**)&qkv, g_qkv);
    cudaGetSymbolAddress((void**)&x1,  g_x1);
    cudaGetSymbolAddress((void**)&ffn, g_ffn);
    cudaGetSymbolAddress((void**)&xc,  g_xc);
    cudaGetSymbolAddress((void**)&x1c, g_x1c);
    cudaGetSymbolAddress((void**)&h,   g_h);
    cudaGetSymbolAddress((void**)&wqt, g_wqt);
    cudaGetSymbolAddress((void**)&w1t, g_w1t);
    cudaGetSymbolAddress((void**)&w2t, g_w2t);

    cudaFuncSetAttribute(gemm_mma_kernel<0,0>,
                         cudaFuncAttributeMaxDynamicSharedMemorySize, GSMEM);
    cudaFuncSetAttribute(gemm_mma_kernel<1,1>,
                         cudaFuncAttributeMaxDynamicSharedMemorySize, GSMEM);

    // one-time converts (tf32 rounding + weight transposes)
    round_tf32_kernel<<<(NTOK * DM / 4 + 255) / 256, 256>>>(x, xc,
                                                            (size_t)NTOK * DM / 4);
    transpose_tf32_kernel<<<dim3(3072 / 32, 1024 / 32), dim3(32, 8)>>>(Wqkv, wqt, 1024, 3072);
    transpose_tf32_kernel<<<dim3(4096 / 32, 1024 / 32), dim3(32, 8)>>>(W1,   w1t, 1024, 4096);
    transpose_tf32_kernel<<<dim3(1024 / 32, 4096 / 32), dim3(32, 8)>>>(W2,   w2t, 4096, 1024);

    // 1) qkv = x @ Wqkv + bqkv
    gemm_mma_kernel<0,0><<<dim3(3072 / 128, NTOK / 256), 256, GSMEM>>>(
        xc, wqt, bqkv, qkv, NTOK, 3072, 1024);
    // 2) x1 = LN(x + headmix(qkv)); also emit tf32-rounded copy
    attn_ln_kernel<<<NTOK, 256>>>(qkv, x, g1, be1, x1, x1c);
    // 3) h = gelu(x1 @ W1 + b1), tf32-rounded out
    gemm_mma_kernel<1,1><<<dim3(4096 / 128, NTOK / 256), 256, GSMEM>>>(
        x1c, w1t, b1, h, NTOK, 4096, 1024);
    // 4) ffn = h @ W2 + b2
    gemm_mma_kernel<0,0><<<dim3(1024 / 128, NTOK / 256), 256, GSMEM>>>(
        h, w2t, b2, ffn, NTOK, 1024, 4096);
    // 5) out = LN(x1 + ffn)
    resid_ln_kernel<<<NTOK, 256>>>(x1, ffn, g2, be2, out);
}